// round 1
// baseline (speedup 1.0000x reference)
#include <cuda_runtime.h>

#define CIN   64
#define HH    56
#define WW    56
#define COUT  64
#define TILE  8
#define KK    3

// CTA: one n, one 8x8 output tile, all 64 output channels.
// 256 threads: tid = cg*64 + py*8 + px ; each thread -> 1 pixel, 16 channels.
// Warp (32 lanes) shares cg -> weight shared-memory reads are broadcast.
__global__ void __launch_bounds__(256)
adder2d_kernel(const float* __restrict__ x,
               const float* __restrict__ w,
               float* __restrict__ out)
{
    __shared__ float sx[CIN][100];      // 10x10 halo tile per channel, 25.6 KB
    __shared__ float sw[8][9][COUT];    // 8-channel weight chunk, 18.4 KB

    const int tid    = threadIdx.x;
    const int px     = tid & 7;
    const int py     = (tid >> 3) & 7;
    const int cg     = tid >> 6;        // 0..3
    const int cobase = cg * 16;

    const int tx0 = blockIdx.x * TILE;
    const int ty0 = blockIdx.y * TILE;
    const int n   = blockIdx.z;

    // ---- stage x tile (with zero halo; padded zeros still contribute |w|) ----
    const float* xn = x + (size_t)n * CIN * HH * WW;
    for (int idx = tid; idx < CIN * 100; idx += 256) {
        int ci = idx / 100;
        int r  = idx - ci * 100;
        int yy = r / 10;
        int xx = r - yy * 10;
        int gy = ty0 + yy - 1;
        int gx = tx0 + xx - 1;
        float v = 0.0f;
        if ((unsigned)gy < (unsigned)HH && (unsigned)gx < (unsigned)WW)
            v = xn[(ci * HH + gy) * WW + gx];
        sx[ci][r] = v;
    }

    float acc[16];
    #pragma unroll
    for (int c = 0; c < 16; ++c) acc[c] = 0.0f;

    // ---- main loop: 8 chunks of 8 input channels ----
    for (int c8 = 0; c8 < 8; ++c8) {
        __syncthreads();   // x tile ready / previous chunk's compute done
        // stage weights: w[co][ci][kh][kw] -> sw[ci_local][k][co]
        for (int idx = tid; idx < 8 * 9 * COUT; idx += 256) {
            int ci_l = idx / (9 * COUT);
            int rest = idx - ci_l * 9 * COUT;
            int k    = rest / COUT;
            int co   = rest - k * COUT;
            sw[ci_l][k][co] = w[(co * CIN + c8 * 8 + ci_l) * 9 + k];
        }
        __syncthreads();

        #pragma unroll 2
        for (int ci_l = 0; ci_l < 8; ++ci_l) {
            const float* bx = &sx[c8 * 8 + ci_l][py * 10 + px];
            float xv[9];
            #pragma unroll
            for (int kh = 0; kh < KK; ++kh)
                #pragma unroll
                for (int kw = 0; kw < KK; ++kw)
                    xv[kh * 3 + kw] = bx[kh * 10 + kw];

            #pragma unroll
            for (int k = 0; k < 9; ++k) {
                #pragma unroll
                for (int c = 0; c < 16; ++c) {
                    // 2 SASS FADDs: diff, then acc -= |diff| (abs as modifier)
                    acc[c] -= fabsf(xv[k] - sw[ci_l][k][cobase + c]);
                }
            }
        }
    }

    // ---- write 16 outputs (H,W divisible by TILE: no bounds checks) ----
    #pragma unroll
    for (int c = 0; c < 16; ++c) {
        out[(((size_t)n * COUT + cobase + c) * HH + (ty0 + py)) * WW + (tx0 + px)] = acc[c];
    }
}

extern "C" void kernel_launch(void* const* d_in, const int* in_sizes, int n_in,
                              void* d_out, int out_size)
{
    const float* x = (const float*)d_in[0];
    const float* w = (const float*)d_in[1];
    float* out     = (float*)d_out;

    dim3 grid(WW / TILE, HH / TILE, 16);   // 7 x 7 x 16 = 784 CTAs
    adder2d_kernel<<<grid, 256>>>(x, w, out);
}